// round 15
// baseline (speedup 1.0000x reference)
#include <cuda_runtime.h>

// LIF, exact k=8 renewal-group folding, HT=256 tiles (128 barriers), dynamic
// smem (141KB). Evolution of the R14 winner (k=4, HT=128, 209.6us).
//
// Exact step: f = set.le(S,th); S = fma(S,f,x)   (bit-exact, proven R4..R14).
// Group of 8 (entry S=u0, inputs x1..x8):
//   u_i = u_{i-1} + x_i  (i=1..7)            speculative no-spike FADD chain
//   a   = fma(u7, [u7<=th], x8)              exact step-8 fold
//   first crossing j = min{ i in 0..6 : u_i > th }  ->  T_j
//   T_j = exact tail of restart at x_{j+1} (helpers run exact STEPX), else a.
// 3-level priority select tree (masks m0..m6, OR-combined pairwise) —
// identical first-crossing-from-left semantics as the proven k=4 tree.
//
// 32 blocks = 16 batches x 2 neuron-halves (32 chains). 320 threads:
//   wid9    : chain warp, 32 groups/tile (256 steps), exports group entries
//   wid5..8 : T-table helpers for tile t+1 (grp % 4 == wid-5)
//   wid3,4  : rerun warps: exact per-step S of tile t-1 -> sbuf (STS.128)
//   wid1,2  : drain warps: sbuf tile t-2 -> global, h-contiguous STG.128
//   wid0    : x stager (tile t+2)
// One __syncthreads per 256-step tile (128 barriers).

#define NB 16
#define NS 256
#define NH 128
#define NN 64
#define NPB 32
#define HT 256
#define NTILES 128
#define GPT 32                      // k=8 groups per tile
#define RS 260                      // sbuf row stride: 16B chunk 65n+q, conflict-free
#define TT (NS * NH)
#define TOTE ((long long)NB * NS * NN * NH)

// dynamic smem layout (float offsets)
#define OFF_TQ   0                               // float4[2][GPT][2][NPB] = 16384 f
#define OFF_ENT  16384                           // float [2][GPT][NPB]    = 2048 f
#define OFF_SBUF (OFF_ENT + 2048)                // float [2][NPB*RS]      = 16640 f
#define OFF_XS   (OFF_SBUF + 2 * NPB * RS)       // float [4][HT]          = 1024 f
#define OFF_THR  (OFF_XS + 4 * HT)               // float [NPB]            = 32 f
#define SMEM_FLOATS (OFF_THR + NPB)
#define SMEM_BYTES  (SMEM_FLOATS * 4)            // 144512 B

#define STEPX(S, XV, TH) do {                                               \
    float f_;                                                               \
    asm("set.le.f32.f32 %0, %1, %2;" : "=f"(f_) : "f"(S), "f"(TH));         \
    asm("fma.rn.f32 %0, %1, %2, %3;" : "=f"(S) : "f"(S), "f"(f_), "f"(XV)); \
} while (0)

__global__ __launch_bounds__(320, 1)
void lif_kernel(const float* __restrict__ inputs,
                const float* __restrict__ threshes,
                const float* __restrict__ acc0,
                float* __restrict__ outbuf)
{
    extern __shared__ float smem[];
    float4* const Tq   = (float4*)(smem + OFF_TQ);    // [2][GPT][2][NPB]
    float*  const ent  = smem + OFF_ENT;              // [2][GPT][NPB]
    float*  const sbuf = smem + OFF_SBUF;             // [2][NPB*RS]
    float*  const xs   = smem + OFF_XS;               // [4][HT]
    float*  const thr  = smem + OFF_THR;              // [NPB]

    const int b    = blockIdx.x >> 1;
    const int g    = blockIdx.x & 1;
    const int tid  = threadIdx.x;
    const int wid  = tid >> 5;
    const int lane = tid & 31;
    const float* xb = inputs + (long long)b * TT;
    float* outp = outbuf;
    float* spkp = outbuf + TOTE;

    // ---- prologue 1: stage x(0), x(1); thresholds ----
    if (wid == 0) {
        *(float4*)&xs[0 * HT + lane * 4]       = *(const float4*)(xb + lane * 4);
        *(float4*)&xs[0 * HT + 128 + lane * 4] = *(const float4*)(xb + 128 + lane * 4);
    }
    if (wid == 3) {
        *(float4*)&xs[1 * HT + lane * 4]       = *(const float4*)(xb + HT + lane * 4);
        *(float4*)&xs[1 * HT + 128 + lane * 4] = *(const float4*)(xb + HT + 128 + lane * 4);
    }
    if (wid == 1) thr[lane] = threshes[g * NPB + lane];
    __syncthreads();

    const float th = thr[lane];              // lane == chain index in all roles

    // ---- prologue 2: T(0) by helpers; chain loads acc0 ----
    float S = 0.0f;
    if (wid >= 5 && wid <= 8) {
        const int hidx = wid - 5;
        #pragma unroll
        for (int gg = 0; gg < 8; ++gg) {
            const int grp = gg * 4 + hidx;
            float xv[8];
            *(float4*)&xv[0] = *(const float4*)&xs[0 * HT + grp * 8];
            *(float4*)&xv[4] = *(const float4*)&xs[0 * HT + grp * 8 + 4];
            float Tv[7];
            #pragma unroll
            for (int j = 6; j >= 0; --j) {
                float P = xv[j];
                #pragma unroll
                for (int i = j + 1; i < 8; ++i) STEPX(P, xv[i], th);
                Tv[j] = P;
            }
            Tq[((0 * GPT + grp) * 2 + 0) * NPB + lane] =
                make_float4(Tv[0], Tv[1], Tv[2], Tv[3]);
            Tq[((0 * GPT + grp) * 2 + 1) * NPB + lane] =
                make_float4(Tv[4], Tv[5], Tv[6], 0.0f);
        }
    }
    if (wid == 9) S = acc0[b * NN + g * NPB + lane];
    __syncthreads();

    for (int t = 0; t <= NTILES + 1; ++t) {
        if (wid == 9) {
            // ================= chain warp: tile t =================
            if (t < NTILES) {
                const float*  __restrict__ xr = xs + (t & 3) * HT;
                const float4* __restrict__ Tt = Tq + (t & 1) * GPT * 2 * NPB;
                float* __restrict__ ed = ent + (t & 1) * GPT * NPB;
                #pragma unroll
                for (int grp = 0; grp < GPT; ++grp) {
                    float4 xa = *(const float4*)&xr[grp * 8];       // broadcast
                    float4 xc = *(const float4*)&xr[grp * 8 + 4];
                    float4 TA = Tt[(grp * 2 + 0) * NPB + lane];     // LDS.128
                    float4 TB = Tt[(grp * 2 + 1) * NPB + lane];
                    ed[grp * NPB + lane] = S;                       // group entry
                    float u1 = S  + xa.x;
                    float u2 = u1 + xa.y;
                    float u3 = u2 + xa.z;
                    float u4 = u3 + xa.w;
                    float u5 = u4 + xc.x;
                    float u6 = u5 + xc.y;
                    float u7 = u6 + xc.z;
                    float Sn;
                    asm("{\n\t"
                        ".reg .pred m0,m2,m4,m6,m01,m23,m45,m0123;\n\t"
                        ".reg .f32  f7,a,s01,s23,s45,s6a,sA,sB;\n\t"
                        "setp.gt.f32 m0, %1, %2;\n\t"          // u0 > th
                        "setp.gt.or.f32 m01, %3, %2, m0;\n\t"  // |u1>th
                        "setp.gt.f32 m2, %4, %2;\n\t"          // u2 > th
                        "setp.gt.or.f32 m23, %5, %2, m2;\n\t"  // |u3>th
                        "setp.gt.f32 m4, %6, %2;\n\t"          // u4 > th
                        "setp.gt.or.f32 m45, %7, %2, m4;\n\t"  // |u5>th
                        "setp.gt.f32 m6, %8, %2;\n\t"          // u6 > th
                        "or.pred m0123, m01, m23;\n\t"
                        "set.le.f32.f32 f7, %9, %2;\n\t"       // [u7<=th]
                        "fma.rn.f32 a, %9, f7, %10;\n\t"       // exact step-8 fold
                        "selp.f32 s01, %11, %12, m0;\n\t"      // m0?T0:T1
                        "selp.f32 s23, %13, %14, m2;\n\t"      // m2?T2:T3
                        "selp.f32 s45, %15, %16, m4;\n\t"      // m4?T4:T5
                        "selp.f32 s6a, %17, a, m6;\n\t"        // m6?T6:a
                        "selp.f32 sA, s01, s23, m01;\n\t"
                        "selp.f32 sB, s45, s6a, m45;\n\t"
                        "selp.f32 %0, sA, sB, m0123;\n\t"      // priority root
                        "}"
                        : "=f"(Sn)
                        : "f"(S), "f"(th), "f"(u1), "f"(u2), "f"(u3),
                          "f"(u4), "f"(u5), "f"(u6), "f"(u7), "f"(xc.w),
                          "f"(TA.x), "f"(TA.y), "f"(TA.z), "f"(TA.w),
                          "f"(TB.x), "f"(TB.y), "f"(TB.z));
                    S = Sn;
                }
            }
        } else if (wid == 0) {
            // ================= x stager: tile t+2 =================
            if (t + 2 < NTILES) {
                const float* src = xb + (t + 2) * HT;
                float* dst = &xs[((t + 2) & 3) * HT];
                *(float4*)&dst[lane * 4]       = *(const float4*)(src + lane * 4);
                *(float4*)&dst[128 + lane * 4] = *(const float4*)(src + 128 + lane * 4);
            }
        } else if (wid >= 5 && wid <= 8) {
            // ================= T helpers: tile t+1 =================
            if (t + 1 < NTILES) {
                const int hidx = wid - 5;
                const float* __restrict__ xr = xs + ((t + 1) & 3) * HT;
                float4* __restrict__ Td = Tq + ((t + 1) & 1) * GPT * 2 * NPB;
                #pragma unroll
                for (int gg = 0; gg < 8; ++gg) {
                    const int grp = gg * 4 + hidx;
                    float xv[8];
                    *(float4*)&xv[0] = *(const float4*)&xr[grp * 8];
                    *(float4*)&xv[4] = *(const float4*)&xr[grp * 8 + 4];
                    float Tv[7];
                    #pragma unroll
                    for (int j = 6; j >= 0; --j) {
                        float P = xv[j];
                        #pragma unroll
                        for (int i = j + 1; i < 8; ++i) STEPX(P, xv[i], th);
                        Tv[j] = P;
                    }
                    Td[(grp * 2 + 0) * NPB + lane] =
                        make_float4(Tv[0], Tv[1], Tv[2], Tv[3]);
                    Td[(grp * 2 + 1) * NPB + lane] =
                        make_float4(Tv[4], Tv[5], Tv[6], 0.0f);
                }
            }
        } else if (wid == 3 || wid == 4) {
            // ================= rerun warps: tile t-1 -> sbuf =================
            if (t >= 1 && t <= NTILES) {
                const int par = wid - 3;
                const int pt  = (t - 1) & 1;
                const float* __restrict__ xr = xs + ((t - 1) & 3) * HT;
                const float* __restrict__ ed = ent + pt * GPT * NPB;
                float* __restrict__ sb = sbuf + pt * NPB * RS;
                #pragma unroll
                for (int gg = 0; gg < 16; ++gg) {
                    const int grp = gg * 2 + par;
                    float  P  = ed[grp * NPB + lane];
                    float4 xa = *(const float4*)&xr[grp * 8];
                    float4 xc = *(const float4*)&xr[grp * 8 + 4];
                    float4 o1, o2;
                    STEPX(P, xa.x, th); o1.x = P;
                    STEPX(P, xa.y, th); o1.y = P;
                    STEPX(P, xa.z, th); o1.z = P;
                    STEPX(P, xa.w, th); o1.w = P;
                    STEPX(P, xc.x, th); o2.x = P;
                    STEPX(P, xc.y, th); o2.y = P;
                    STEPX(P, xc.z, th); o2.z = P;
                    STEPX(P, xc.w, th); o2.w = P;
                    *(float4*)&sb[lane * RS + grp * 8]     = o1;   // STS.128
                    *(float4*)&sb[lane * RS + grp * 8 + 4] = o2;
                }
            }
        } else {
            // ========== drain warps (wid 1,2): sbuf tile t-2 -> global ==========
            if (t >= 2) {
                const int dt = t - 2;                 // tile covers s = 2dt, 2dt+1
                const int pt = dt & 1;
                const int idx0 = (wid - 1) * 1024;
                const float* __restrict__ sb = sbuf + pt * NPB * RS;
                #pragma unroll
                for (int i = 0; i < 32; ++i) {
                    int idx = idx0 + i * 32 + lane;   // 0..2047
                    int sl  = idx >> 10;              // s_local 0/1
                    int rem = idx & 1023;
                    int n = rem >> 5, q = rem & 31;
                    float4 v = *(const float4*)&sb[n * RS + sl * 128 + q * 4];
                    float tn = thr[n];
                    float f0, f1, f2, f3;
                    asm("set.gt.f32.f32 %0, %1, %2;" : "=f"(f0) : "f"(v.x), "f"(tn));
                    asm("set.gt.f32.f32 %0, %1, %2;" : "=f"(f1) : "f"(v.y), "f"(tn));
                    asm("set.gt.f32.f32 %0, %1, %2;" : "=f"(f2) : "f"(v.z), "f"(tn));
                    asm("set.gt.f32.f32 %0, %1, %2;" : "=f"(f3) : "f"(v.w), "f"(tn));
                    float4 o = make_float4(v.x * f0, v.y * f1, v.z * f2, v.w * f3);
                    float4 k = make_float4(f0, f1, f2, f3);
                    float* ob = outp +
                        (((long long)b * NS + dt * 2 + sl) * NN + g * NPB + n) * NH;
                    *(float4*)(ob + q * 4)        = o;   // STG.128 coalesced
                    *(float4*)(ob + TOTE + q * 4) = k;
                }
            }
        }
        __syncthreads();
    }
}

extern "C" void kernel_launch(void* const* d_in, const int* in_sizes, int n_in,
                              void* d_out, int out_size)
{
    const float* inputs   = (const float*)d_in[0];  // [B,S,H]
    const float* threshes = (const float*)d_in[1];  // [N]
    const float* acc0     = (const float*)d_in[2];  // [B,N]
    float* out = (float*)d_out;                     // outs then spikes (f32)

    cudaFuncSetAttribute(lif_kernel,
                         cudaFuncAttributeMaxDynamicSharedMemorySize,
                         SMEM_BYTES);
    lif_kernel<<<NB * 2, 320, SMEM_BYTES>>>(inputs, threshes, acc0, out);
}